// round 1
// baseline (speedup 1.0000x reference)
#include <cuda_runtime.h>

// Problem constants
#define B_   32
#define N_   1024
#define C_   768
#define H_   12
#define DH   64
#define M_   (B_ * N_)        // 32768 rows
#define QKVC (3 * C_)         // 2304 qkv columns

// Scratch: qkv laid out [s][b][h][n][d] (s=0:q,1:k,2:v), ctx laid out [b][n][c]
__device__ float g_qkv[(size_t)3 * B_ * H_ * N_ * DH];   // 302 MB
__device__ float g_ctx[(size_t)M_ * C_];                 // 100 MB

// ---------------------------------------------------------------------------
// Kernel 1: QKV projection GEMM  Y = x @ w_qkv + b_qkv, scattered to g_qkv
// Tiling: BM=128, BN=128, BK=16, 256 threads, 8x8 per-thread register tile.
// ---------------------------------------------------------------------------
__global__ __launch_bounds__(256) void qkv_gemm(const float* __restrict__ x,
                                                const float* __restrict__ w,
                                                const float* __restrict__ bias) {
    __shared__ float As[16][132];   // [k][m], padded stride 132 (mult of 4)
    __shared__ float Bs[16][132];   // [k][n]

    const int tid = threadIdx.x;
    const int m0  = blockIdx.y * 128;
    const int n0  = blockIdx.x * 128;

    const int a_row  = tid >> 2;       // 0..63
    const int a_col4 = tid & 3;        // 0..3  (float4 within 16 cols)
    const int b_row  = tid >> 5;       // 0..7
    const int b_col4 = tid & 31;       // 0..31 (float4 within 128 cols)

    const int tx = tid & 15;
    const int ty = tid >> 4;

    float acc[8][8];
#pragma unroll
    for (int i = 0; i < 8; i++)
#pragma unroll
        for (int j = 0; j < 8; j++) acc[i][j] = 0.f;

    for (int k0 = 0; k0 < C_; k0 += 16) {
        // Load A tile (128x16), store transposed As[k][m]
#pragma unroll
        for (int hh = 0; hh < 2; hh++) {
            int r = a_row + hh * 64;
            float4 v = *(const float4*)&x[(size_t)(m0 + r) * C_ + k0 + a_col4 * 4];
            As[a_col4 * 4 + 0][r] = v.x;
            As[a_col4 * 4 + 1][r] = v.y;
            As[a_col4 * 4 + 2][r] = v.z;
            As[a_col4 * 4 + 3][r] = v.w;
        }
        // Load B tile (16x128), natural layout Bs[k][n]
#pragma unroll
        for (int hh = 0; hh < 2; hh++) {
            int r = b_row + hh * 8;
            *(float4*)&Bs[r][b_col4 * 4] =
                *(const float4*)&w[(size_t)(k0 + r) * QKVC + n0 + b_col4 * 4];
        }
        __syncthreads();

#pragma unroll
        for (int k = 0; k < 16; k++) {
            float a[8], bb[8];
            *(float4*)&a[0]  = *(const float4*)&As[k][ty * 8];
            *(float4*)&a[4]  = *(const float4*)&As[k][ty * 8 + 4];
            *(float4*)&bb[0] = *(const float4*)&Bs[k][tx * 8];
            *(float4*)&bb[4] = *(const float4*)&Bs[k][tx * 8 + 4];
#pragma unroll
            for (int i = 0; i < 8; i++)
#pragma unroll
                for (int j = 0; j < 8; j++) acc[i][j] += a[i] * bb[j];
        }
        __syncthreads();
    }

    // Scatter epilogue: col -> (s, h, d); row -> (b, n)
#pragma unroll
    for (int i = 0; i < 8; i++) {
        int m = m0 + ty * 8 + i;
        int b = m >> 10;
        int n = m & 1023;
#pragma unroll
        for (int j = 0; j < 8; j++) {
            int col = n0 + tx * 8 + j;
            int s   = col / C_;
            int rem = col - s * C_;
            int h   = rem >> 6;
            int d   = rem & 63;
            size_t dst = ((((size_t)s * B_ + b) * H_ + h) * N_ + n) * DH + d;
            g_qkv[dst] = acc[i][j] + bias[col];
        }
    }
}

// ---------------------------------------------------------------------------
// Kernel 2: flash attention. One block handles (b,h) x 64 query rows.
// 256 threads as 16x16 grid; 4x4 register micro-tiles for S and O.
// ---------------------------------------------------------------------------
struct AttnSmem {
    float Qs[64][64];     // [d][r]   (transposed)
    float Ks[64][64];     // [d][c]   (transposed)
    float Vs[64][64];     // [j][dv]  (natural)
    float Pst[64][68];    // [c][r]   (transposed, padded)
    float row_m[64];
    float row_l[64];
    float row_alpha[64];
};

__global__ __launch_bounds__(256) void attn_kernel() {
    extern __shared__ char smem_raw[];
    AttnSmem& sm = *reinterpret_cast<AttnSmem*>(smem_raw);

    const int bh = blockIdx.y;            // 0..383  (= b*H + h)
    const int r0 = blockIdx.x * 64;       // query-row tile origin
    const int b  = bh / H_;
    const int h  = bh - b * H_;

    const float* qp = g_qkv + ((size_t)0 * B_ * H_ + bh) * N_ * DH;
    const float* kp = g_qkv + ((size_t)1 * B_ * H_ + bh) * N_ * DH;
    const float* vp = g_qkv + ((size_t)2 * B_ * H_ + bh) * N_ * DH;

    const int tid = threadIdx.x;
    const int tx  = tid & 15;
    const int ty  = tid >> 4;

    // Load Q tile transposed: Qs[d][r]
    {
        int r   = tid & 63;
        int d4b = tid >> 6;   // 0..3
#pragma unroll
        for (int it = 0; it < 4; it++) {
            int d4   = d4b * 4 + it;   // 0..15
            float4 v = *(const float4*)&qp[(size_t)(r0 + r) * DH + d4 * 4];
            sm.Qs[d4 * 4 + 0][r] = v.x;
            sm.Qs[d4 * 4 + 1][r] = v.y;
            sm.Qs[d4 * 4 + 2][r] = v.z;
            sm.Qs[d4 * 4 + 3][r] = v.w;
        }
    }
    if (tid < 64) { sm.row_m[tid] = -1e30f; sm.row_l[tid] = 0.f; }

    float o[4][4];
#pragma unroll
    for (int i = 0; i < 4; i++)
#pragma unroll
        for (int j = 0; j < 4; j++) o[i][j] = 0.f;

    for (int c0 = 0; c0 < N_; c0 += 64) {
        __syncthreads();   // previous tile's P@V done; Qs load done on iter 0
        // Load K (transposed) and V (natural) tiles
        {
            int r   = tid & 63;
            int d4b = tid >> 6;
#pragma unroll
            for (int it = 0; it < 4; it++) {
                int d4    = d4b * 4 + it;
                float4 kv = *(const float4*)&kp[(size_t)(c0 + r) * DH + d4 * 4];
                sm.Ks[d4 * 4 + 0][r] = kv.x;
                sm.Ks[d4 * 4 + 1][r] = kv.y;
                sm.Ks[d4 * 4 + 2][r] = kv.z;
                sm.Ks[d4 * 4 + 3][r] = kv.w;
                *(float4*)&sm.Vs[r][d4 * 4] =
                    *(const float4*)&vp[(size_t)(c0 + r) * DH + d4 * 4];
            }
        }
        __syncthreads();

        // S = (Q K^T) * scale  -> 4x4 register tile per thread
        float s[4][4];
#pragma unroll
        for (int i = 0; i < 4; i++)
#pragma unroll
            for (int j = 0; j < 4; j++) s[i][j] = 0.f;
#pragma unroll
        for (int d = 0; d < 64; d++) {
            float a[4], bb[4];
            *(float4*)a  = *(const float4*)&sm.Qs[d][ty * 4];
            *(float4*)bb = *(const float4*)&sm.Ks[d][tx * 4];
#pragma unroll
            for (int i = 0; i < 4; i++)
#pragma unroll
                for (int j = 0; j < 4; j++) s[i][j] += a[i] * bb[j];
        }
#pragma unroll
        for (int i = 0; i < 4; i++)
#pragma unroll
            for (int j = 0; j < 4; j++)
                sm.Pst[tx * 4 + j][ty * 4 + i] = s[i][j] * 0.125f;
        __syncthreads();

        // Online softmax row pass: 4 threads per row, 16 keys each
        {
            int r   = tid >> 2;
            int qid = tid & 3;
            float vals[16];
            float mx = -1e30f;
#pragma unroll
            for (int j = 0; j < 16; j++) {
                float v = sm.Pst[qid + j * 4][r];
                vals[j] = v;
                mx = fmaxf(mx, v);
            }
            mx = fmaxf(mx, __shfl_xor_sync(0xffffffffu, mx, 1));
            mx = fmaxf(mx, __shfl_xor_sync(0xffffffffu, mx, 2));
            float m_old = sm.row_m[r];
            float m_new = fmaxf(m_old, mx);
            float sum = 0.f;
#pragma unroll
            for (int j = 0; j < 16; j++) {
                float p = __expf(vals[j] - m_new);
                sm.Pst[qid + j * 4][r] = p;
                sum += p;
            }
            sum += __shfl_xor_sync(0xffffffffu, sum, 1);
            sum += __shfl_xor_sync(0xffffffffu, sum, 2);
            if (qid == 0) {
                float alpha = __expf(m_old - m_new);
                sm.row_alpha[r] = alpha;
                sm.row_l[r]     = sm.row_l[r] * alpha + sum;
                sm.row_m[r]     = m_new;
            }
        }
        __syncthreads();

        // Rescale O, then O += P @ V
        float al[4];
#pragma unroll
        for (int i = 0; i < 4; i++) al[i] = sm.row_alpha[ty * 4 + i];
#pragma unroll
        for (int i = 0; i < 4; i++)
#pragma unroll
            for (int j = 0; j < 4; j++) o[i][j] *= al[i];

#pragma unroll
        for (int j64 = 0; j64 < 64; j64++) {
            float a[4], bb[4];
            *(float4*)a  = *(const float4*)&sm.Pst[j64][ty * 4];
            *(float4*)bb = *(const float4*)&sm.Vs[j64][tx * 4];
#pragma unroll
            for (int i = 0; i < 4; i++)
#pragma unroll
                for (int j = 0; j < 4; j++) o[i][j] += a[i] * bb[j];
        }
    }
    __syncthreads();

    // Finalize: O /= l, write ctx[b][n][h*64 + dv]
    float inv[4];
#pragma unroll
    for (int i = 0; i < 4; i++) inv[i] = 1.f / sm.row_l[ty * 4 + i];
#pragma unroll
    for (int i = 0; i < 4; i++) {
        int n = r0 + ty * 4 + i;
        float4 w4;
        w4.x = o[i][0] * inv[i];
        w4.y = o[i][1] * inv[i];
        w4.z = o[i][2] * inv[i];
        w4.w = o[i][3] * inv[i];
        *(float4*)&g_ctx[(size_t)(b * N_ + n) * C_ + h * DH + tx * 4] = w4;
    }
}

// ---------------------------------------------------------------------------
// Kernel 3: output projection GEMM  out = ctx @ w_proj + b_proj
// ---------------------------------------------------------------------------
__global__ __launch_bounds__(256) void proj_gemm(const float* __restrict__ w,
                                                 const float* __restrict__ bias,
                                                 float* __restrict__ out) {
    __shared__ float As[16][132];
    __shared__ float Bs[16][132];

    const int tid = threadIdx.x;
    const int m0  = blockIdx.y * 128;
    const int n0  = blockIdx.x * 128;

    const int a_row  = tid >> 2;
    const int a_col4 = tid & 3;
    const int b_row  = tid >> 5;
    const int b_col4 = tid & 31;

    const int tx = tid & 15;
    const int ty = tid >> 4;

    float acc[8][8];
#pragma unroll
    for (int i = 0; i < 8; i++)
#pragma unroll
        for (int j = 0; j < 8; j++) acc[i][j] = 0.f;

    for (int k0 = 0; k0 < C_; k0 += 16) {
#pragma unroll
        for (int hh = 0; hh < 2; hh++) {
            int r = a_row + hh * 64;
            float4 v = *(const float4*)&g_ctx[(size_t)(m0 + r) * C_ + k0 + a_col4 * 4];
            As[a_col4 * 4 + 0][r] = v.x;
            As[a_col4 * 4 + 1][r] = v.y;
            As[a_col4 * 4 + 2][r] = v.z;
            As[a_col4 * 4 + 3][r] = v.w;
        }
#pragma unroll
        for (int hh = 0; hh < 2; hh++) {
            int r = b_row + hh * 8;
            *(float4*)&Bs[r][b_col4 * 4] =
                *(const float4*)&w[(size_t)(k0 + r) * C_ + n0 + b_col4 * 4];
        }
        __syncthreads();

#pragma unroll
        for (int k = 0; k < 16; k++) {
            float a[8], bb[8];
            *(float4*)&a[0]  = *(const float4*)&As[k][ty * 8];
            *(float4*)&a[4]  = *(const float4*)&As[k][ty * 8 + 4];
            *(float4*)&bb[0] = *(const float4*)&Bs[k][tx * 8];
            *(float4*)&bb[4] = *(const float4*)&Bs[k][tx * 8 + 4];
#pragma unroll
            for (int i = 0; i < 8; i++)
#pragma unroll
                for (int j = 0; j < 8; j++) acc[i][j] += a[i] * bb[j];
        }
        __syncthreads();
    }

#pragma unroll
    for (int i = 0; i < 8; i++) {
        int m = m0 + ty * 8 + i;
#pragma unroll
        for (int j4 = 0; j4 < 2; j4++) {
            int col = n0 + tx * 8 + j4 * 4;
            float4 w4;
            w4.x = acc[i][j4 * 4 + 0] + bias[col + 0];
            w4.y = acc[i][j4 * 4 + 1] + bias[col + 1];
            w4.z = acc[i][j4 * 4 + 2] + bias[col + 2];
            w4.w = acc[i][j4 * 4 + 3] + bias[col + 3];
            *(float4*)&out[(size_t)m * C_ + col] = w4;
        }
    }
}

// ---------------------------------------------------------------------------
// Launch
// ---------------------------------------------------------------------------
extern "C" void kernel_launch(void* const* d_in, const int* in_sizes, int n_in,
                              void* d_out, int out_size) {
    const float* x      = (const float*)d_in[0];
    const float* w_qkv  = (const float*)d_in[1];
    const float* b_qkv  = (const float*)d_in[2];
    const float* w_proj = (const float*)d_in[3];
    const float* b_proj = (const float*)d_in[4];
    float* out = (float*)d_out;

    (void)in_sizes; (void)n_in; (void)out_size;

    cudaFuncSetAttribute(attn_kernel, cudaFuncAttributeMaxDynamicSharedMemorySize,
                         (int)sizeof(AttnSmem));

    dim3 blk(256);
    qkv_gemm<<<dim3(QKVC / 128, M_ / 128), blk>>>(x, w_qkv, b_qkv);
    attn_kernel<<<dim3(N_ / 64, B_ * H_), blk, sizeof(AttnSmem)>>>();
    proj_gemm<<<dim3(C_ / 128, M_ / 128), blk>>>(w_proj, b_proj, out);
}

// round 2
// speedup vs baseline: 3.2060x; 3.2060x over previous
#include <cuda_runtime.h>
#include <cstdint>

#define B_   32
#define N_   1024
#define C_   768
#define H_   12
#define DH   64
#define M_   (B_ * N_)
#define QKVC (3 * C_)

// Scratch: qkv [s][b][h][n][d], ctx [b][n][c]
__device__ float g_qkv[(size_t)3 * B_ * H_ * N_ * DH];
__device__ float g_ctx[(size_t)M_ * C_];

// ---------------------------------------------------------------------------
// helpers
// ---------------------------------------------------------------------------
__device__ __forceinline__ unsigned smem_u32(const void* p) {
    return (unsigned)__cvta_generic_to_shared(p);
}
__device__ __forceinline__ unsigned f2tf(float x) {
    unsigned r; asm("cvt.rna.tf32.f32 %0, %1;" : "=r"(r) : "f"(x)); return r;
}
__device__ __forceinline__ void ldsm4(unsigned& r0, unsigned& r1, unsigned& r2,
                                      unsigned& r3, unsigned a) {
    asm volatile("ldmatrix.sync.aligned.m8n8.x4.shared.b16 {%0,%1,%2,%3}, [%4];"
                 : "=r"(r0), "=r"(r1), "=r"(r2), "=r"(r3) : "r"(a));
}
__device__ __forceinline__ void mma8(float* d, const unsigned* a, const unsigned* b) {
    asm volatile("mma.sync.aligned.m16n8k8.row.col.f32.tf32.tf32.f32 "
                 "{%0,%1,%2,%3},{%4,%5,%6,%7},{%8,%9},{%0,%1,%2,%3};"
                 : "+f"(d[0]), "+f"(d[1]), "+f"(d[2]), "+f"(d[3])
                 : "r"(a[0]), "r"(a[1]), "r"(a[2]), "r"(a[3]),
                   "r"(b[0]), "r"(b[1]));
}

// ---------------------------------------------------------------------------
// GEMM: out = A(MxK) @ W(KxN) + bias.  MODE 0: scatter into g_qkv (N=2304)
//                                      MODE 1: write Cout (N=768), A = g_ctx
// Tiles: BM=128, BN=128, BK=32; 8 warps of 64x32; tf32 mma m16n8k8.
// ---------------------------------------------------------------------------
template <int NCOLS, int MODE>
__global__ __launch_bounds__(256) void gemm_tf32(const float* __restrict__ Ain,
                                                 const float* __restrict__ Bw,
                                                 const float* __restrict__ bias,
                                                 float* __restrict__ Cout) {
    __shared__ float As[128 * 36];   // [m][k], stride 36
    __shared__ float Bs[128 * 36];   // [n][k] (B^T), stride 36

    const int tid  = threadIdx.x;
    const int lane = tid & 31;
    const int warp = tid >> 5;
    const int m0 = blockIdx.y * 128;
    const int n0 = blockIdx.x * 128;
    const int wm = (warp >> 2) * 64;
    const int wn = (warp & 3) * 32;

    const float* A = (MODE == 0) ? Ain : g_ctx;

    float acc[4][4][4];
#pragma unroll
    for (int i = 0; i < 4; i++)
#pragma unroll
        for (int j = 0; j < 4; j++)
#pragma unroll
            for (int r = 0; r < 4; r++) acc[i][j][r] = 0.f;

    const int bk = (lane & 15) | ((warp & 1) << 4);          // 0..31 k row
    const int bc = (lane >> 4) + ((warp >> 1) << 1);         // n granule base
    const int mat = lane >> 3;

    for (int k0 = 0; k0 < C_; k0 += 32) {
        // Stage A: [m][k] natural, float4 along k
#pragma unroll
        for (int i = 0; i < 4; i++) {
            int G = tid + 256 * i;
            int row = G >> 3, kg = G & 7;
            float4 v = *(const float4*)&A[(size_t)(m0 + row) * C_ + k0 + kg * 4];
            uint4 u; u.x = f2tf(v.x); u.y = f2tf(v.y); u.z = f2tf(v.z); u.w = f2tf(v.w);
            *reinterpret_cast<uint4*>(&As[row * 36 + kg * 4]) = u;
        }
        // Stage B transposed: Bs[n][k]
#pragma unroll
        for (int it = 0; it < 4; it++) {
            int c = bc + 8 * it;
            float4 v = *(const float4*)&Bw[(size_t)(k0 + bk) * NCOLS + n0 + c * 4];
            Bs[(4 * c + 0) * 36 + bk] = __uint_as_float(f2tf(v.x));
            Bs[(4 * c + 1) * 36 + bk] = __uint_as_float(f2tf(v.y));
            Bs[(4 * c + 2) * 36 + bk] = __uint_as_float(f2tf(v.z));
            Bs[(4 * c + 3) * 36 + bk] = __uint_as_float(f2tf(v.w));
        }
        __syncthreads();

#pragma unroll
        for (int ks = 0; ks < 4; ks++) {
            unsigned af[4][4], bf[2][4];
#pragma unroll
            for (int mt = 0; mt < 4; mt++) {
                int row = wm + mt * 16 + (lane & 7) + ((mat & 1) << 3);
                int col = ks * 8 + ((mat >> 1) << 2);
                ldsm4(af[mt][0], af[mt][1], af[mt][2], af[mt][3],
                      smem_u32(&As[row * 36 + col]));
            }
#pragma unroll
            for (int p = 0; p < 2; p++) {
                int row = wn + p * 16 + (lane & 7) + ((mat >> 1) << 3);
                int col = ks * 8 + ((mat & 1) << 2);
                ldsm4(bf[p][0], bf[p][1], bf[p][2], bf[p][3],
                      smem_u32(&Bs[row * 36 + col]));
            }
#pragma unroll
            for (int mt = 0; mt < 4; mt++)
#pragma unroll
                for (int nt = 0; nt < 4; nt++)
                    mma8(acc[mt][nt], af[mt], &bf[nt >> 1][(nt & 1) * 2]);
        }
        __syncthreads();
    }

    // Epilogue
#pragma unroll
    for (int mt = 0; mt < 4; mt++) {
        int rbase = m0 + wm + mt * 16 + (lane >> 2);
#pragma unroll
        for (int nt = 0; nt < 4; nt++) {
            int cn = n0 + wn + nt * 8 + (lane & 3) * 2;
            float bv0 = bias[cn], bv1 = bias[cn + 1];
            float2 lo = make_float2(acc[mt][nt][0] + bv0, acc[mt][nt][1] + bv1);
            float2 hi = make_float2(acc[mt][nt][2] + bv0, acc[mt][nt][3] + bv1);
            if (MODE == 0) {
                int s = cn / C_;
                int rem = cn - s * C_;
                int h = rem >> 6, d = rem & 63;
                int bq = rbase >> 10, nn = rbase & 1023;
                size_t base = (((size_t)s * B_ + bq) * H_ + h) * N_;
                *(float2*)&g_qkv[(base + nn) * DH + d]     = lo;
                *(float2*)&g_qkv[(base + nn + 8) * DH + d] = hi;
            } else {
                *(float2*)&Cout[(size_t)rbase * NCOLS + cn]       = lo;
                *(float2*)&Cout[(size_t)(rbase + 8) * NCOLS + cn] = hi;
            }
        }
    }
}

// ---------------------------------------------------------------------------
// Flash attention, tf32 mma. CTA = 128 queries of one (b,h); 64-key tiles.
// 8 warps; each warp owns a 16-row query band (full softmax within warp).
// ---------------------------------------------------------------------------
#define ATTN_SMEM ((128 * 68 + 64 * 68 + 64 * 68 + 128 * 68) * 4)

__global__ __launch_bounds__(256) void attn_tf32() {
    extern __shared__ float sm[];
    float* Qs  = sm;                    // [128][68]  q rows x d
    float* Ks  = Qs + 128 * 68;        // [64][68]   key rows x d
    float* Vst = Ks + 64 * 68;         // [64][68]   d rows x key (V^T)
    float* Ps  = Vst + 64 * 68;        // [128][68]  q rows x key

    const int tid  = threadIdx.x;
    const int lane = tid & 31;
    const int warp = tid >> 5;
    const int bh = blockIdx.y;
    const int r0 = blockIdx.x * 128;
    const int b  = bh / H_;
    const int h  = bh - b * H_;

    const float* qp = g_qkv + (size_t)bh * N_ * DH;
    const float* kp = g_qkv + ((size_t)B_ * H_ + bh) * N_ * DH;
    const float* vp = g_qkv + ((size_t)2 * B_ * H_ + bh) * N_ * DH;

    // Stage Q once (tf32)
    {
        int r = tid >> 1, gb = (tid & 1) * 8;
#pragma unroll
        for (int i = 0; i < 8; i++) {
            int g = gb + i;
            float4 v = *(const float4*)&qp[(size_t)(r0 + r) * DH + g * 4];
            uint4 u; u.x = f2tf(v.x); u.y = f2tf(v.y); u.z = f2tf(v.z); u.w = f2tf(v.w);
            *reinterpret_cast<uint4*>(&Qs[r * 68 + g * 4]) = u;
        }
    }

    float s[8][4], o[8][4];
#pragma unroll
    for (int t = 0; t < 8; t++) { o[t][0] = o[t][1] = o[t][2] = o[t][3] = 0.f; }
    float m_lo = -1e30f, m_hi = -1e30f, l_lo = 0.f, l_hi = 0.f;

    const int band = warp * 16;
    const int mat  = lane >> 3;
    const int vkey = (lane & 15) | ((warp & 1) << 4);
    const int vgb  = (lane >> 4) + ((warp >> 1) << 1);

    for (int c0 = 0; c0 < N_; c0 += 64) {
        __syncthreads();
        // Stage K [key][d]
        {
            int r = tid >> 2, gb = (tid & 3) * 4;
#pragma unroll
            for (int i = 0; i < 4; i++) {
                int g = gb + i;
                float4 v = *(const float4*)&kp[(size_t)(c0 + r) * DH + g * 4];
                uint4 u; u.x = f2tf(v.x); u.y = f2tf(v.y); u.z = f2tf(v.z); u.w = f2tf(v.w);
                *reinterpret_cast<uint4*>(&Ks[r * 68 + g * 4]) = u;
            }
        }
        // Stage V transposed [d][key]
#pragma unroll
        for (int kit = 0; kit < 2; kit++) {
            int key = vkey + 32 * kit;
#pragma unroll
            for (int git = 0; git < 2; git++) {
                int g = vgb + 8 * git;
                float4 v = *(const float4*)&vp[(size_t)(c0 + key) * DH + g * 4];
                Vst[(4 * g + 0) * 68 + key] = __uint_as_float(f2tf(v.x));
                Vst[(4 * g + 1) * 68 + key] = __uint_as_float(f2tf(v.y));
                Vst[(4 * g + 2) * 68 + key] = __uint_as_float(f2tf(v.z));
                Vst[(4 * g + 3) * 68 + key] = __uint_as_float(f2tf(v.w));
            }
        }
        __syncthreads();

        // S = Q @ K^T
#pragma unroll
        for (int t = 0; t < 8; t++) { s[t][0] = s[t][1] = s[t][2] = s[t][3] = 0.f; }
#pragma unroll
        for (int kk = 0; kk < 8; kk++) {
            unsigned af[4], bf[4][4];
            int arow = band + (lane & 7) + ((mat & 1) << 3);
            int acol = kk * 8 + ((mat >> 1) << 2);
            ldsm4(af[0], af[1], af[2], af[3], smem_u32(&Qs[arow * 68 + acol]));
#pragma unroll
            for (int p = 0; p < 4; p++) {
                int brow = p * 16 + (lane & 7) + ((mat >> 1) << 3);
                int bcol = kk * 8 + ((mat & 1) << 2);
                ldsm4(bf[p][0], bf[p][1], bf[p][2], bf[p][3],
                      smem_u32(&Ks[brow * 68 + bcol]));
            }
#pragma unroll
            for (int nt = 0; nt < 8; nt++) mma8(s[nt], af, &bf[nt >> 1][(nt & 1) * 2]);
        }

        // Online softmax (rows: lane/4 and lane/4+8 of this warp's band)
        float mx_lo = -1e30f, mx_hi = -1e30f;
#pragma unroll
        for (int t = 0; t < 8; t++) {
            s[t][0] *= 0.125f; s[t][1] *= 0.125f; s[t][2] *= 0.125f; s[t][3] *= 0.125f;
            mx_lo = fmaxf(mx_lo, fmaxf(s[t][0], s[t][1]));
            mx_hi = fmaxf(mx_hi, fmaxf(s[t][2], s[t][3]));
        }
        mx_lo = fmaxf(mx_lo, __shfl_xor_sync(0xffffffffu, mx_lo, 1));
        mx_lo = fmaxf(mx_lo, __shfl_xor_sync(0xffffffffu, mx_lo, 2));
        mx_hi = fmaxf(mx_hi, __shfl_xor_sync(0xffffffffu, mx_hi, 1));
        mx_hi = fmaxf(mx_hi, __shfl_xor_sync(0xffffffffu, mx_hi, 2));
        float mn_lo = fmaxf(m_lo, mx_lo), mn_hi = fmaxf(m_hi, mx_hi);
        float al_lo = __expf(m_lo - mn_lo), al_hi = __expf(m_hi - mn_hi);
        m_lo = mn_lo; m_hi = mn_hi;
        float sum_lo = 0.f, sum_hi = 0.f;
#pragma unroll
        for (int t = 0; t < 8; t++) {
            s[t][0] = __expf(s[t][0] - mn_lo); s[t][1] = __expf(s[t][1] - mn_lo);
            s[t][2] = __expf(s[t][2] - mn_hi); s[t][3] = __expf(s[t][3] - mn_hi);
            sum_lo += s[t][0] + s[t][1];
            sum_hi += s[t][2] + s[t][3];
            o[t][0] *= al_lo; o[t][1] *= al_lo; o[t][2] *= al_hi; o[t][3] *= al_hi;
        }
        sum_lo += __shfl_xor_sync(0xffffffffu, sum_lo, 1);
        sum_lo += __shfl_xor_sync(0xffffffffu, sum_lo, 2);
        sum_hi += __shfl_xor_sync(0xffffffffu, sum_hi, 1);
        sum_hi += __shfl_xor_sync(0xffffffffu, sum_hi, 2);
        l_lo = l_lo * al_lo + sum_lo;
        l_hi = l_hi * al_hi + sum_hi;

        // Write P (tf32) to own band — warp-local, no block barrier
        {
            int prow = band + (lane >> 2);
            int pcol = (lane & 3) * 2;
#pragma unroll
            for (int t = 0; t < 8; t++) {
                *reinterpret_cast<uint2*>(&Ps[prow * 68 + t * 8 + pcol]) =
                    make_uint2(f2tf(s[t][0]), f2tf(s[t][1]));
                *reinterpret_cast<uint2*>(&Ps[(prow + 8) * 68 + t * 8 + pcol]) =
                    make_uint2(f2tf(s[t][2]), f2tf(s[t][3]));
            }
        }
        __syncwarp();

        // O += P @ V
#pragma unroll
        for (int kk = 0; kk < 8; kk++) {
            unsigned af[4], bf[4][4];
            int arow = band + (lane & 7) + ((mat & 1) << 3);
            int acol = kk * 8 + ((mat >> 1) << 2);
            ldsm4(af[0], af[1], af[2], af[3], smem_u32(&Ps[arow * 68 + acol]));
#pragma unroll
            for (int p = 0; p < 4; p++) {
                int brow = p * 16 + (lane & 7) + ((mat >> 1) << 3);
                int bcol = kk * 8 + ((mat & 1) << 2);
                ldsm4(bf[p][0], bf[p][1], bf[p][2], bf[p][3],
                      smem_u32(&Vst[brow * 68 + bcol]));
            }
#pragma unroll
            for (int nt = 0; nt < 8; nt++) mma8(o[nt], af, &bf[nt >> 1][(nt & 1) * 2]);
        }
    }

    // Finalize: O /= l, write ctx[b][n][h*64+d]
    float inv_lo = 1.f / l_lo, inv_hi = 1.f / l_hi;
    int n_lo = r0 + band + (lane >> 2);
#pragma unroll
    for (int t = 0; t < 8; t++) {
        int d0 = t * 8 + (lane & 3) * 2;
        size_t addr = (size_t)(b * N_ + n_lo) * C_ + h * DH + d0;
        *(float2*)&g_ctx[addr]          = make_float2(o[t][0] * inv_lo, o[t][1] * inv_lo);
        *(float2*)&g_ctx[addr + 8 * C_] = make_float2(o[t][2] * inv_hi, o[t][3] * inv_hi);
    }
}

// ---------------------------------------------------------------------------
// Launch
// ---------------------------------------------------------------------------
extern "C" void kernel_launch(void* const* d_in, const int* in_sizes, int n_in,
                              void* d_out, int out_size) {
    const float* x      = (const float*)d_in[0];
    const float* w_qkv  = (const float*)d_in[1];
    const float* b_qkv  = (const float*)d_in[2];
    const float* w_proj = (const float*)d_in[3];
    const float* b_proj = (const float*)d_in[4];
    float* out = (float*)d_out;
    (void)in_sizes; (void)n_in; (void)out_size;

    cudaFuncSetAttribute(attn_tf32, cudaFuncAttributeMaxDynamicSharedMemorySize,
                         ATTN_SMEM);

    gemm_tf32<QKVC, 0><<<dim3(QKVC / 128, M_ / 128), 256>>>(x, w_qkv, b_qkv, nullptr);
    attn_tf32<<<dim3(N_ / 128, B_ * H_), 256, ATTN_SMEM>>>();
    gemm_tf32<C_, 1><<<dim3(C_ / 128, M_ / 128), 256>>>(nullptr, w_proj, b_proj, out);
}

// round 3
// speedup vs baseline: 3.2768x; 1.0221x over previous
#include <cuda_runtime.h>
#include <cstdint>

#define B_   32
#define N_   1024
#define C_   768
#define H_   12
#define DH   64
#define M_   (B_ * N_)
#define QKVC (3 * C_)

__device__ float g_qkv[(size_t)3 * B_ * H_ * N_ * DH];
__device__ float g_ctx[(size_t)M_ * C_];

// ---------------------------------------------------------------------------
// helpers
// ---------------------------------------------------------------------------
__device__ __forceinline__ unsigned smem_u32(const void* p) {
    return (unsigned)__cvta_generic_to_shared(p);
}
__device__ __forceinline__ unsigned f2tf(float x) {
    unsigned r; asm("cvt.rna.tf32.f32 %0, %1;" : "=r"(r) : "f"(x)); return r;
}
__device__ __forceinline__ void ldsm4(unsigned& r0, unsigned& r1, unsigned& r2,
                                      unsigned& r3, unsigned a) {
    asm volatile("ldmatrix.sync.aligned.m8n8.x4.shared.b16 {%0,%1,%2,%3}, [%4];"
                 : "=r"(r0), "=r"(r1), "=r"(r2), "=r"(r3) : "r"(a));
}
// ldmatrix + convert fragments to tf32
__device__ __forceinline__ void ldsm4c(unsigned* r, unsigned a) {
    ldsm4(r[0], r[1], r[2], r[3], a);
    r[0] = f2tf(__uint_as_float(r[0]));
    r[1] = f2tf(__uint_as_float(r[1]));
    r[2] = f2tf(__uint_as_float(r[2]));
    r[3] = f2tf(__uint_as_float(r[3]));
}
__device__ __forceinline__ void mma8(float* d, const unsigned* a, const unsigned* b) {
    asm volatile("mma.sync.aligned.m16n8k8.row.col.f32.tf32.tf32.f32 "
                 "{%0,%1,%2,%3},{%4,%5,%6,%7},{%8,%9},{%0,%1,%2,%3};"
                 : "+f"(d[0]), "+f"(d[1]), "+f"(d[2]), "+f"(d[3])
                 : "r"(a[0]), "r"(a[1]), "r"(a[2]), "r"(a[3]),
                   "r"(b[0]), "r"(b[1]));
}
__device__ __forceinline__ void cpa16(unsigned dst, const void* src) {
    asm volatile("cp.async.cg.shared.global [%0], [%1], 16;" :: "r"(dst), "l"(src));
}
__device__ __forceinline__ void cpa_commit() { asm volatile("cp.async.commit_group;"); }
__device__ __forceinline__ void cpa_wait0()  { asm volatile("cp.async.wait_group 0;"); }

// ---------------------------------------------------------------------------
// GEMM: BM=128, BN=256, BK=32; 8 warps of 64x64; double-buffered cp.async.
// MODE 0: out scattered to g_qkv (NCOLS=2304). MODE 1: A=g_ctx, out=Cout.
// ---------------------------------------------------------------------------
#define GEMM_SMEM ((2 * 128 * 36 + 2 * 256 * 36) * 4)

template <int NCOLS, int MODE>
__global__ __launch_bounds__(256) void gemm_tf32(const float* __restrict__ Ain,
                                                 const float* __restrict__ Bw,
                                                 const float* __restrict__ bias,
                                                 float* __restrict__ Cout) {
    extern __shared__ float sm[];
    float* As[2] = { sm, sm + 128 * 36 };
    float* Bs[2] = { sm + 2 * 128 * 36, sm + 2 * 128 * 36 + 256 * 36 };

    const int tid  = threadIdx.x;
    const int lane = tid & 31;
    const int warp = tid >> 5;
    const int m0 = blockIdx.y * 128;
    const int n0 = blockIdx.x * 256;
    const int wm = (warp & 1) * 64;
    const int wn = (warp >> 1) * 64;
    const int mat = lane >> 3;

    const float* A = (MODE == 0) ? Ain : g_ctx;

    // staging maps
    const int bk = tid & 31;        // B k-row
    const int bg = tid >> 5;        // B n-granule base (0..7)

    float acc[4][8][4];
#pragma unroll
    for (int i = 0; i < 4; i++)
#pragma unroll
        for (int j = 0; j < 8; j++)
#pragma unroll
            for (int r = 0; r < 4; r++) acc[i][j][r] = 0.f;

    // ---- prologue: stage tile 0 ----
#pragma unroll
    for (int i = 0; i < 4; i++) {
        int G = tid + 256 * i, row = G >> 3, kg = G & 7;
        cpa16(smem_u32(&As[0][row * 36 + kg * 4]),
              &A[(size_t)(m0 + row) * C_ + kg * 4]);
    }
    cpa_commit();
#pragma unroll
    for (int i = 0; i < 8; i++) {
        int g = bg + 8 * i;
        float4 v = *(const float4*)&Bw[(size_t)bk * NCOLS + n0 + g * 4];
        Bs[0][(4 * g + 0) * 36 + bk] = v.x;
        Bs[0][(4 * g + 1) * 36 + bk] = v.y;
        Bs[0][(4 * g + 2) * 36 + bk] = v.z;
        Bs[0][(4 * g + 3) * 36 + bk] = v.w;
    }
    cpa_wait0();
    __syncthreads();

    const int KT = C_ / 32;
    for (int kt = 0; kt < KT; kt++) {
        const int cur = kt & 1, nxt = cur ^ 1;
        float4 breg[8];
        if (kt + 1 < KT) {
            int k0n = (kt + 1) * 32;
#pragma unroll
            for (int i = 0; i < 4; i++) {
                int G = tid + 256 * i, row = G >> 3, kg = G & 7;
                cpa16(smem_u32(&As[nxt][row * 36 + kg * 4]),
                      &A[(size_t)(m0 + row) * C_ + k0n + kg * 4]);
            }
            cpa_commit();
#pragma unroll
            for (int i = 0; i < 8; i++) {
                int g = bg + 8 * i;
                breg[i] = *(const float4*)&Bw[(size_t)(k0n + bk) * NCOLS + n0 + g * 4];
            }
        }

        // ---- mma over cur ----
#pragma unroll
        for (int ks = 0; ks < 4; ks++) {
            unsigned af[4][4], bf[4][4];
#pragma unroll
            for (int mt = 0; mt < 4; mt++) {
                int row = wm + mt * 16 + (lane & 7) + ((mat & 1) << 3);
                int col = ks * 8 + ((mat >> 1) << 2);
                ldsm4c(af[mt], smem_u32(&As[cur][row * 36 + col]));
            }
#pragma unroll
            for (int p = 0; p < 4; p++) {
                int row = wn + p * 16 + (lane & 7) + ((mat >> 1) << 3);
                int col = ks * 8 + ((mat & 1) << 2);
                ldsm4c(bf[p], smem_u32(&Bs[cur][row * 36 + col]));
            }
#pragma unroll
            for (int mt = 0; mt < 4; mt++)
#pragma unroll
                for (int nt = 0; nt < 8; nt++)
                    mma8(acc[mt][nt], af[mt], &bf[nt >> 1][(nt & 1) * 2]);
        }

        if (kt + 1 < KT) {
#pragma unroll
            for (int i = 0; i < 8; i++) {
                int g = bg + 8 * i;
                Bs[nxt][(4 * g + 0) * 36 + bk] = breg[i].x;
                Bs[nxt][(4 * g + 1) * 36 + bk] = breg[i].y;
                Bs[nxt][(4 * g + 2) * 36 + bk] = breg[i].z;
                Bs[nxt][(4 * g + 3) * 36 + bk] = breg[i].w;
            }
            cpa_wait0();
        }
        __syncthreads();
    }

    // ---- epilogue ----
#pragma unroll
    for (int mt = 0; mt < 4; mt++) {
        int rbase = m0 + wm + mt * 16 + (lane >> 2);
#pragma unroll
        for (int nt = 0; nt < 8; nt++) {
            int cn = n0 + wn + nt * 8 + (lane & 3) * 2;
            float bv0 = bias[cn], bv1 = bias[cn + 1];
            float2 lo = make_float2(acc[mt][nt][0] + bv0, acc[mt][nt][1] + bv1);
            float2 hi = make_float2(acc[mt][nt][2] + bv0, acc[mt][nt][3] + bv1);
            if (MODE == 0) {
                int s = cn / C_;
                int rem = cn - s * C_;
                int h = rem >> 6, d = rem & 63;
                int bq = rbase >> 10, nn = rbase & 1023;
                size_t base = (((size_t)s * B_ + bq) * H_ + h) * N_;
                *(float2*)&g_qkv[(base + nn) * DH + d]     = lo;
                *(float2*)&g_qkv[(base + nn + 8) * DH + d] = hi;
            } else {
                *(float2*)&Cout[(size_t)rbase * NCOLS + cn]       = lo;
                *(float2*)&Cout[(size_t)(rbase + 8) * NCOLS + cn] = hi;
            }
        }
    }
}

// ---------------------------------------------------------------------------
// Flash attention. CTA = 256 queries of one (b,h); 8 warps x 32-row bands;
// 64-key tiles; warp-local softmax; cp.async K, reg-prefetch V.
// ---------------------------------------------------------------------------
#define ATTN_SMEM ((256 * 68 + 2 * 64 * 68 + 64 * 68 + 256 * 68) * 4)

__global__ __launch_bounds__(256) void attn_tf32() {
    extern __shared__ float sm[];
    float* Qs    = sm;                       // [256][68]
    float* Ks[2] = { Qs + 256 * 68, Qs + 256 * 68 + 64 * 68 };
    float* Vst   = Qs + 256 * 68 + 2 * 64 * 68;   // [64][68]  (V^T)
    float* Ps    = Vst + 64 * 68;            // [256][68]

    const int tid  = threadIdx.x;
    const int lane = tid & 31;
    const int warp = tid >> 5;
    const int bh = blockIdx.y;
    const int r0 = blockIdx.x * 256;
    const int b  = bh / H_;
    const int h  = bh - b * H_;

    const float* qp = g_qkv + (size_t)bh * N_ * DH;
    const float* kp = g_qkv + ((size_t)B_ * H_ + bh) * N_ * DH;
    const float* vp = g_qkv + ((size_t)2 * B_ * H_ + bh) * N_ * DH;

    const int band = warp * 32;
    const int mat  = lane >> 3;
    const int vkey = tid & 63;          // V transpose staging
    const int vgb  = tid >> 6;          // 0..3

    // ---- prologue: Q (cp.async), K0 (cp.async), V0 (regs) ----
#pragma unroll
    for (int i = 0; i < 16; i++) {
        int G = tid + 256 * i, row = G >> 4, g = G & 15;
        cpa16(smem_u32(&Qs[row * 68 + g * 4]),
              &qp[(size_t)(r0 + row) * DH + g * 4]);
    }
#pragma unroll
    for (int i = 0; i < 4; i++) {
        int G = tid + 256 * i, row = G >> 4, g = G & 15;
        cpa16(smem_u32(&Ks[0][row * 68 + g * 4]),
              &kp[(size_t)row * DH + g * 4]);
    }
    cpa_commit();
    float4 vreg[4];
#pragma unroll
    for (int i = 0; i < 4; i++) {
        int g = vgb + 4 * i;
        vreg[i] = *(const float4*)&vp[(size_t)vkey * DH + g * 4];
    }

    float o[2][8][4];
#pragma unroll
    for (int mt = 0; mt < 2; mt++)
#pragma unroll
        for (int nt = 0; nt < 8; nt++)
#pragma unroll
            for (int r = 0; r < 4; r++) o[mt][nt][r] = 0.f;
    float m_st[4] = { -1e30f, -1e30f, -1e30f, -1e30f };
    float l_st[4] = { 0.f, 0.f, 0.f, 0.f };

    cpa_wait0();
    __syncthreads();

    for (int t = 0; t < 16; t++) {
        const int cur = t & 1, nxt = cur ^ 1;
        // store V(t) from regs (transposed)
#pragma unroll
        for (int i = 0; i < 4; i++) {
            int g = vgb + 4 * i;
            Vst[(4 * g + 0) * 68 + vkey] = vreg[i].x;
            Vst[(4 * g + 1) * 68 + vkey] = vreg[i].y;
            Vst[(4 * g + 2) * 68 + vkey] = vreg[i].z;
            Vst[(4 * g + 3) * 68 + vkey] = vreg[i].w;
        }
        __syncthreads();

        if (t + 1 < 16) {
            int c0n = (t + 1) * 64;
#pragma unroll
            for (int i = 0; i < 4; i++) {
                int G = tid + 256 * i, row = G >> 4, g = G & 15;
                cpa16(smem_u32(&Ks[nxt][row * 68 + g * 4]),
                      &kp[(size_t)(c0n + row) * DH + g * 4]);
            }
            cpa_commit();
#pragma unroll
            for (int i = 0; i < 4; i++) {
                int g = vgb + 4 * i;
                vreg[i] = *(const float4*)&vp[(size_t)(c0n + vkey) * DH + g * 4];
            }
        }

        // ---- S = Q K^T ----
        float s[2][8][4];
#pragma unroll
        for (int mt = 0; mt < 2; mt++)
#pragma unroll
            for (int nt = 0; nt < 8; nt++)
#pragma unroll
                for (int r = 0; r < 4; r++) s[mt][nt][r] = 0.f;
#pragma unroll
        for (int kk = 0; kk < 8; kk++) {
            unsigned af[2][4], bf[4][4];
#pragma unroll
            for (int mt = 0; mt < 2; mt++) {
                int arow = band + mt * 16 + (lane & 7) + ((mat & 1) << 3);
                int acol = kk * 8 + ((mat >> 1) << 2);
                ldsm4c(af[mt], smem_u32(&Qs[arow * 68 + acol]));
            }
#pragma unroll
            for (int p = 0; p < 4; p++) {
                int brow = p * 16 + (lane & 7) + ((mat >> 1) << 3);
                int bcol = kk * 8 + ((mat & 1) << 2);
                ldsm4c(bf[p], smem_u32(&Ks[cur][brow * 68 + bcol]));
            }
#pragma unroll
            for (int mt = 0; mt < 2; mt++)
#pragma unroll
                for (int nt = 0; nt < 8; nt++)
                    mma8(s[mt][nt], af[mt], &bf[nt >> 1][(nt & 1) * 2]);
        }

        // ---- online softmax (4 row groups per thread) ----
#pragma unroll
        for (int g = 0; g < 4; g++) {
            int mt = g >> 1, c = (g & 1) * 2;
            float mx = -1e30f;
#pragma unroll
            for (int nt = 0; nt < 8; nt++) {
                s[mt][nt][c]   *= 0.125f;
                s[mt][nt][c+1] *= 0.125f;
                mx = fmaxf(mx, fmaxf(s[mt][nt][c], s[mt][nt][c+1]));
            }
            mx = fmaxf(mx, __shfl_xor_sync(0xffffffffu, mx, 1));
            mx = fmaxf(mx, __shfl_xor_sync(0xffffffffu, mx, 2));
            float mn = fmaxf(m_st[g], mx);
            float al = __expf(m_st[g] - mn);
            m_st[g] = mn;
            float sum = 0.f;
#pragma unroll
            for (int nt = 0; nt < 8; nt++) {
                s[mt][nt][c]   = __expf(s[mt][nt][c]   - mn);
                s[mt][nt][c+1] = __expf(s[mt][nt][c+1] - mn);
                sum += s[mt][nt][c] + s[mt][nt][c+1];
                o[mt][nt][c]   *= al;
                o[mt][nt][c+1] *= al;
            }
            sum += __shfl_xor_sync(0xffffffffu, sum, 1);
            sum += __shfl_xor_sync(0xffffffffu, sum, 2);
            l_st[g] = l_st[g] * al + sum;
        }

        // ---- write P (raw f32) to warp-private band ----
        {
            int prow = band + (lane >> 2);
            int pcol = (lane & 3) * 2;
#pragma unroll
            for (int mt = 0; mt < 2; mt++)
#pragma unroll
                for (int nt = 0; nt < 8; nt++) {
                    *(float2*)&Ps[(prow + mt * 16) * 68 + nt * 8 + pcol] =
                        make_float2(s[mt][nt][0], s[mt][nt][1]);
                    *(float2*)&Ps[(prow + mt * 16 + 8) * 68 + nt * 8 + pcol] =
                        make_float2(s[mt][nt][2], s[mt][nt][3]);
                }
        }
        __syncwarp();

        // ---- O += P @ V ----
#pragma unroll
        for (int kk = 0; kk < 8; kk++) {
            unsigned af[2][4], bf[4][4];
#pragma unroll
            for (int mt = 0; mt < 2; mt++) {
                int arow = band + mt * 16 + (lane & 7) + ((mat & 1) << 3);
                int acol = kk * 8 + ((mat >> 1) << 2);
                ldsm4c(af[mt], smem_u32(&Ps[arow * 68 + acol]));
            }
#pragma unroll
            for (int p = 0; p < 4; p++) {
                int brow = p * 16 + (lane & 7) + ((mat >> 1) << 3);
                int bcol = kk * 8 + ((mat & 1) << 2);
                ldsm4c(bf[p], smem_u32(&Vst[brow * 68 + bcol]));
            }
#pragma unroll
            for (int mt = 0; mt < 2; mt++)
#pragma unroll
                for (int nt = 0; nt < 8; nt++)
                    mma8(o[mt][nt], af[mt], &bf[nt >> 1][(nt & 1) * 2]);
        }

        if (t + 1 < 16) cpa_wait0();
        __syncthreads();
    }

    // ---- finalize ----
#pragma unroll
    for (int g = 0; g < 4; g++) {
        int mt = g >> 1, c = (g & 1) * 2;
        float inv = 1.f / l_st[g];
        int n = r0 + band + mt * 16 + (lane >> 2) + (g & 1) * 8;
#pragma unroll
        for (int nt = 0; nt < 8; nt++) {
            int d0 = nt * 8 + (lane & 3) * 2;
            *(float2*)&g_ctx[(size_t)(b * N_ + n) * C_ + h * DH + d0] =
                make_float2(o[mt][nt][c] * inv, o[mt][nt][c+1] * inv);
        }
    }
}

// ---------------------------------------------------------------------------
// Launch
// ---------------------------------------------------------------------------
extern "C" void kernel_launch(void* const* d_in, const int* in_sizes, int n_in,
                              void* d_out, int out_size) {
    const float* x      = (const float*)d_in[0];
    const float* w_qkv  = (const float*)d_in[1];
    const float* b_qkv  = (const float*)d_in[2];
    const float* w_proj = (const float*)d_in[3];
    const float* b_proj = (const float*)d_in[4];
    float* out = (float*)d_out;
    (void)in_sizes; (void)n_in; (void)out_size;

    cudaFuncSetAttribute(gemm_tf32<QKVC, 0>,
                         cudaFuncAttributeMaxDynamicSharedMemorySize, GEMM_SMEM);
    cudaFuncSetAttribute(gemm_tf32<C_, 1>,
                         cudaFuncAttributeMaxDynamicSharedMemorySize, GEMM_SMEM);
    cudaFuncSetAttribute(attn_tf32,
                         cudaFuncAttributeMaxDynamicSharedMemorySize, ATTN_SMEM);

    gemm_tf32<QKVC, 0><<<dim3(QKVC / 256, M_ / 128), 256, GEMM_SMEM>>>(x, w_qkv, b_qkv, nullptr);
    attn_tf32<<<dim3(N_ / 256, B_ * H_), 256, ATTN_SMEM>>>();
    gemm_tf32<C_, 1><<<dim3(C_ / 256, M_ / 128), 256, GEMM_SMEM>>>(nullptr, w_proj, b_proj, out);
}